// round 15
// baseline (speedup 1.0000x reference)
#include <cuda_runtime.h>
#include <cuda_fp16.h>
#include <cstdint>
#include <math.h>

// Problem sizes (fixed)
#define NE   32
#define HD   2048
#define ID   1536
#define NTOK 1024
#define TOPK 8
#define NP   (NTOK*TOPK)
#define BM   256
#define MAXMT 64

// ---------------- device scratch ----------------
__device__ int    g_perm[NP];
__device__ float  g_pw[NP];
__device__ int    g_off[NE+1];
__device__ int    g_mt_e[MAXMT];
__device__ int    g_mt_r[MAXMT];
__device__ int    g_mt_n[MAXMT];          // tile m-rows (32..256, mult of 32)
__device__ int    g_nmt;
__device__ __half g_xh[(size_t)NTOK*HD];  // 4 MB fp16 hidden states
__device__ __half g_act[(size_t)NP*ID];   // 24 MB fp16 activations

// ---------------- helpers ----------------
__device__ __forceinline__ uint32_t smem_u32(const void* p){
  uint32_t a;
  asm("{ .reg .u64 t; cvta.to.shared.u64 t, %1; cvt.u32.u64 %0, t; }" : "=r"(a) : "l"(p));
  return a;
}
__device__ __forceinline__ uint32_t f22h(float lo, float hi){
  uint32_t r; asm("cvt.rn.f16x2.f32 %0, %1, %2;" : "=r"(r) : "f"(hi), "f"(lo));
  return r;
}
__device__ __forceinline__ void ldsm4(uint32_t* r, uint32_t a){
  asm volatile("ldmatrix.sync.aligned.m8n8.x4.shared.b16 {%0,%1,%2,%3}, [%4];"
    : "=r"(r[0]),"=r"(r[1]),"=r"(r[2]),"=r"(r[3]) : "r"(a));
}
__device__ __forceinline__ void sts128(uint32_t a, uint4 v){
  asm volatile("st.shared.v4.b32 [%0], {%1,%2,%3,%4};"
    :: "r"(a), "r"(v.x), "r"(v.y), "r"(v.z), "r"(v.w));
}
__device__ __forceinline__ void cpasync16(uint32_t dst, const void* src){
  asm volatile("cp.async.cg.shared.global [%0], [%1], 16;" :: "r"(dst), "l"(src));
}
#define CP_COMMIT() asm volatile("cp.async.commit_group;" ::: "memory")
#define CP_WAIT0()  asm volatile("cp.async.wait_group 0;" ::: "memory")
__device__ __forceinline__ void mma16816(float* d, const uint32_t* a, const uint32_t* b){
  asm volatile(
    "mma.sync.aligned.m16n8k16.row.col.f32.f16.f16.f32 "
    "{%0,%1,%2,%3},{%4,%5,%6,%7},{%8,%9},{%0,%1,%2,%3};"
    : "+f"(d[0]),"+f"(d[1]),"+f"(d[2]),"+f"(d[3])
    : "r"(a[0]),"r"(a[1]),"r"(a[2]),"r"(a[3]), "r"(b[0]),"r"(b[1]));
}
__device__ __forceinline__ void red2(float* p, float x, float y){
  asm volatile("red.global.add.v2.f32 [%0], {%1,%2};" :: "l"(p), "f"(x), "f"(y) : "memory");
}
// 64B-pitch swizzle (32 fp16 per row), for gemm2
__device__ __forceinline__ uint32_t swz(uint32_t r){
  return (r << 6) ^ (((r >> 1) & 3u) << 4);
}
// 128B-pitch swizzle (64 fp16 per row), for gemm1
__device__ __forceinline__ uint32_t swz128(uint32_t r, uint32_t cb){
  return (r << 7) + (((cb ^ (r & 7u))) << 4);
}
// load 8 fp32 -> 16B fp16
__device__ __forceinline__ uint4 ld8cvt(const float* s){
  float4 u = *(const float4*)s; float4 v = *(const float4*)(s+4);
  uint4 r; r.x = f22h(u.x,u.y); r.y = f22h(u.z,u.w);
  r.z = f22h(v.x,v.y); r.w = f22h(v.z,v.w);
  return r;
}

// ---------------- small kernels ----------------
// prep: zero output + convert X to fp16 (merged)
__global__ void prep_kernel(const float* __restrict__ X, float4* __restrict__ out){
  int i = blockIdx.x*256 + threadIdx.x;
  if (i < NTOK*HD/2){
    float2 v = ((const float2*)X)[i];
    ((uint32_t*)g_xh)[i] = f22h(v.x, v.y);
  }
  if (i < NTOK*HD/4) out[i] = make_float4(0.f,0.f,0.f,0.f);
}

__global__ void route_kernel(const int* __restrict__ idx, const float* __restrict__ w){
  __shared__ int cnt[NE];
  __shared__ int cur[NE];
  __shared__ int soff[NE+1];
  int tid = threadIdx.x;
  if (tid < NE) cnt[tid] = 0;
  __syncthreads();
  for (int i = tid; i < NP; i += blockDim.x) atomicAdd(&cnt[idx[i]], 1);
  __syncthreads();
  if (tid == 0){
    int s = 0, nm = 0;
    for (int e = 0; e < NE; e++){
      soff[e] = s;
      for (int j = 0; j < cnt[e]; j += BM){
        int rem = cnt[e] - j;
        int sz  = (rem >= BM) ? BM : ((rem + 31) & ~31);
        g_mt_e[nm] = e; g_mt_r[nm] = s + j; g_mt_n[nm] = sz; nm++;
      }
      s += cnt[e];
    }
    soff[NE] = s;
    g_nmt = nm;
  }
  __syncthreads();
  if (tid <= NE) g_off[tid] = soff[tid];
  if (tid <  NE) cur[tid]  = soff[tid];
  __syncthreads();
  for (int i = tid; i < NP; i += blockDim.x){
    int e = idx[i];
    int p = atomicAdd(&cur[e], 1);
    g_perm[p] = i / TOPK;
    g_pw[p]   = w[i];
  }
}

// =================== GEMM1 ===================
// Block <=256 tokens x 64 inter-channels (gate+up). BK=64 per stage.
// Stage: A [0,32K) 256 rows, G [32K,40K) 64 rows, U [40K,48K). 2 stages = 96KB.
// 512 thr (16 warps = 8m x 2n), 1 CTA/SM. Warp tile 32m x 32ch dual.
#define G1_STAGE 49152
#define G1_SMEM  98304
#define G1_NKT   (HD/64)   // 32

__global__ __launch_bounds__(512,1) void gemm1_kernel(const float* __restrict__ GU)
{
  const int mt = blockIdx.x;
  if (mt >= g_nmt) return;
  const int e = g_mt_e[mt], row0 = g_mt_r[mt], pend = g_off[e+1];
  const int mrows = g_mt_n[mt];
  const int i0 = blockIdx.y * 64;

  extern __shared__ char smem[];
  const uint32_t sb = smem_u32(smem);
  const int t = threadIdx.x, lane = t & 31, wid = t >> 5;
  const int mw = wid >> 1, nw = wid & 1;       // 8m x 2n warps
  const bool mact = (mw*32 < mrows);

  // ---- producer A: 2 thr/row, 256 rows, 64B per thread (4 x 16B cp.async) --
  const int lrA = t >> 1, qA = t & 1;
  const bool aact = (lrA < mrows);
  int pa = row0 + lrA; int pc = (pa < pend) ? pa : row0;
  const __half* srcA = g_xh + (size_t)g_perm[pc]*HD + qA*32;
  uint32_t oA[4];
  #pragma unroll
  for (int j = 0; j < 4; j++) oA[j] = swz128(lrA, 4*qA + j);

  // ---- producer G/U: 8 thr/row, 64 rows, 8 fp32 (one 16B dst) per thread ---
  const int lrB = t >> 3, qB = t & 7;
  const float* gu_e = GU + (size_t)e*(2*ID)*HD;
  const float* srcG = gu_e + (size_t)(i0 + lrB)*HD + qB*8;
  const float* srcU = gu_e + (size_t)(ID + i0 + lrB)*HD + qB*8;
  const uint32_t oG = 32768 + swz128(lrB, qB);
  const uint32_t oU = oG + 8192;

  // ---- consumer fragment bases ----
  const uint32_t hi = lane >> 4;
  const uint32_t r0 = mw*32 + (lane & 15), r1 = r0 + 16;
  const uint32_t a0b = r0 << 7, a0x = r0 & 7;
  const uint32_t a1b = r1 << 7, a1x = r1 & 7;
  const int brl = (lane & 7) + (((lane >> 4) & 1) << 3);
  const uint32_t bh = (lane >> 3) & 1;
  const uint32_t rg0 = nw*32 + brl, rg1 = rg0 + 16;
  const uint32_t g0b = 32768 + (rg0 << 7), g0x = rg0 & 7;
  const uint32_t g1b = 32768 + (rg1 << 7), g1x = rg1 & 7;

  float accg[2][4][4] = {}, accu[2][4][4] = {};

  // ---- prologue: fill stage 0 ----
  {
    if (aact){
      #pragma unroll
      for (int j = 0; j < 4; j++) cpasync16(sb + oA[j], srcA + j*8);
    }
    CP_COMMIT();
    sts128(sb + oG, ld8cvt(srcG));
    sts128(sb + oU, ld8cvt(srcU));
    CP_WAIT0();
  }
  __syncthreads();

  for (int kt = 0; kt < G1_NKT; kt++){
    const uint32_t cur = sb + (uint32_t)(kt & 1)*G1_STAGE;
    const uint32_t nxt = sb + (uint32_t)((kt + 1) & 1)*G1_STAGE;
    const bool more = (kt + 1 < G1_NKT);
    const int ko = (kt + 1)*64;

    uint4 fG, fU;
    if (more){
      if (aact){
        #pragma unroll
        for (int j = 0; j < 4; j++) cpasync16(nxt + oA[j], srcA + ko + j*8);
      }
      CP_COMMIT();
      fG = ld8cvt(srcG + ko);
    }
    // ks 0,1 (rotated per m-warp)
    if (mact){
      #pragma unroll
      for (int ks = 0; ks < 2; ks++){
        const uint32_t ksr = (uint32_t)((ks + mw) & 3);
        const uint32_t cbA = 2*ksr + hi, cbB = 2*ksr + bh;
        uint32_t A0[4], A1[4], Bg[8], Bu[8];
        ldsm4(A0,   cur + a0b + ((cbA ^ a0x) << 4));
        ldsm4(A1,   cur + a1b + ((cbA ^ a1x) << 4));
        ldsm4(Bg,   cur + g0b + ((cbB ^ g0x) << 4));
        ldsm4(Bg+4, cur + g1b + ((cbB ^ g1x) << 4));
        ldsm4(Bu,   cur + g0b + 8192 + ((cbB ^ g0x) << 4));
        ldsm4(Bu+4, cur + g1b + 8192 + ((cbB ^ g1x) << 4));
        #pragma unroll
        for (int ni = 0; ni < 4; ni++){
          mma16816(accg[0][ni], A0, Bg + ni*2);
          mma16816(accg[1][ni], A1, Bg + ni*2);
          mma16816(accu[0][ni], A0, Bu + ni*2);
          mma16816(accu[1][ni], A1, Bu + ni*2);
        }
      }
    }
    if (more){
      sts128(nxt + oG, fG);
      fU = ld8cvt(srcU + ko);
    }
    // ks 2,3
    if (mact){
      #pragma unroll
      for (int ks = 2; ks < 4; ks++){
        const uint32_t ksr = (uint32_t)((ks + mw) & 3);
        const uint32_t cbA = 2*ksr + hi, cbB = 2*ksr + bh;
        uint32_t A0[4], A1[4], Bg[8], Bu[8];
        ldsm4(A0,   cur + a0b + ((cbA ^ a0x) << 4));
        ldsm4(A1,   cur + a1b + ((cbA ^ a1x) << 4));
        ldsm4(Bg,   cur + g0b + ((cbB ^ g0x) << 4));
        ldsm4(Bg+4, cur + g1b + ((cbB ^ g1x) << 4));
        ldsm4(Bu,   cur + g0b + 8192 + ((cbB ^ g0x) << 4));
        ldsm4(Bu+4, cur + g1b + 8192 + ((cbB ^ g1x) << 4));
        #pragma unroll
        for (int ni = 0; ni < 4; ni++){
          mma16816(accg[0][ni], A0, Bg + ni*2);
          mma16816(accg[1][ni], A1, Bg + ni*2);
          mma16816(accu[0][ni], A0, Bu + ni*2);
          mma16816(accu[1][ni], A1, Bu + ni*2);
        }
      }
    }
    if (more){
      sts128(nxt + oU, fU);
      CP_WAIT0();
      __syncthreads();
    }
  }

  // ---- epilogue: silu(gate)*up*router_weight -> g_act fp16 ----
  if (mact){
    const int g = lane >> 2, c = lane & 3;
    #pragma unroll
    for (int mi = 0; mi < 2; mi++){
      #pragma unroll
      for (int h = 0; h < 2; h++){
        int R = mw*32 + mi*16 + g + 8*h;
        int p = row0 + R;
        if (p < pend){
          float wgt = g_pw[p];
          __half* arow = g_act + (size_t)p*ID + i0 + nw*32 + 2*c;
          #pragma unroll
          for (int ni = 0; ni < 4; ni++){
            float gv0 = accg[mi][ni][2*h],   gv1 = accg[mi][ni][2*h+1];
            float uv0 = accu[mi][ni][2*h],   uv1 = accu[mi][ni][2*h+1];
            float o0 = wgt * (gv0 / (1.f + __expf(-gv0))) * uv0;
            float o1 = wgt * (gv1 / (1.f + __expf(-gv1))) * uv1;
            *(__half2*)(arow + ni*8) = __floats2half2_rn(o0, o1);
          }
        }
      }
    }
  }
}

// =================== GEMM2 ===================
// Block <=256 act-rows x 128 h-channels. BK=32 per stage.
// Stage: A [0,16K) 256 rows x 64B, B [16K,24K) 128 rows. 2 stages = 48KB.
// 512 thr (16 warps = 8m x 2n), 1 CTA/SM. Warp tile 32m x 64n.
#define G2_STAGE 24576
#define G2_SMEM  49152
#define G2_NKT   (ID/32)   // 48

__global__ __launch_bounds__(512,1) void gemm2_kernel(const float* __restrict__ DW,
                                                      float* __restrict__ out)
{
  const int mt = blockIdx.x;
  if (mt >= g_nmt) return;
  const int e = g_mt_e[mt], row0 = g_mt_r[mt], pend = g_off[e+1];
  const int mrows = g_mt_n[mt];
  const int h0 = blockIdx.y * 128;

  extern __shared__ char smem[];
  const uint32_t sb = smem_u32(smem);
  const int t = threadIdx.x, lane = t & 31, wid = t >> 5;
  const int mw = wid >> 1, nw = wid & 1;       // 8m x 2n warps (32m x 64n each)
  const bool mact = (mw*32 < mrows);

  // ---- producer A: 2 thr/row, 256 rows, 32B per thread (2 x 16B cp.async) --
  // NOTE: g_act is indexed by grouped row p directly (NO g_perm!)
  const int lrA = t >> 1, qA = t & 1;
  const bool aact = (lrA < mrows);
  int pa = row0 + lrA; int pcl = (pa < pend) ? pa : row0;
  const __half* srcA = g_act + (size_t)pcl*ID + qA*16;
  const uint32_t oA0 = swz(lrA) ^ ((uint32_t)(2*qA) << 4);
  const uint32_t oA1 = swz(lrA) ^ ((uint32_t)(2*qA+1) << 4);

  // ---- producer B: 4 thr/row, 128 rows, 8 fp32 (one 16B dst) per thread ----
  const int lrB = t >> 2, qB = t & 3;
  const float* srcB = DW + (size_t)e*HD*ID + (size_t)(h0 + lrB)*ID + qB*8;
  const uint32_t oB = 16384 + (swz(lrB) ^ ((uint32_t)qB << 4));

  // ---- consumer fragment offsets ----
  const uint32_t ca = (uint32_t)(lane >> 4) << 4;
  const uint32_t pa0 = swz(mw*32 + (lane & 15)) ^ ca;
  const uint32_t pa1 = swz(mw*32 + 16 + (lane & 15)) ^ ca;
  const int brl = (lane & 7) + (((lane >> 4) & 1) << 3);
  const uint32_t cb = (uint32_t)((lane >> 3) & 1) << 4;
  uint32_t pb[4];
  #pragma unroll
  for (int j = 0; j < 4; j++)
    pb[j] = swz(256 + nw*64 + j*16 + brl) ^ cb;

  float acc[2][8][4] = {};

  // ---- prologue: fill stage 0 ----
  {
    if (aact){ cpasync16(sb + oA0, srcA); cpasync16(sb + oA1, srcA + 8); }
    CP_COMMIT();
    sts128(sb + oB, ld8cvt(srcB));
    CP_WAIT0();
  }
  __syncthreads();

  for (int kt = 0; kt < G2_NKT; kt++){
    const uint32_t sbuf = sb + (uint32_t)(kt & 1)*G2_STAGE;
    const uint32_t dbuf = sb + (uint32_t)((kt + 1) & 1)*G2_STAGE;
    const bool more = (kt + 1 < G2_NKT);
    const int ko = (kt + 1)*32;

    uint4 fB;
    if (more){
      if (aact){ cpasync16(dbuf + oA0, srcA + ko); cpasync16(dbuf + oA1, srcA + ko + 8); }
      CP_COMMIT();
      fB = ld8cvt(srcB + ko);
    }
    if (mact){
      #pragma unroll
      for (int ks = 0; ks < 2; ks++){
        const uint32_t k5 = ((uint32_t)((ks + wid) & 1)) << 5;   // rotated
        uint32_t A0[4], A1[4], B[16];
        ldsm4(A0, sbuf + (pa0 ^ k5));
        ldsm4(A1, sbuf + (pa1 ^ k5));
        #pragma unroll
        for (int j = 0; j < 4; j++) ldsm4(B + j*4, sbuf + (pb[j] ^ k5));
        #pragma unroll
        for (int ni = 0; ni < 8; ni++){
          mma16816(acc[0][ni], A0, B + ni*2);
          mma16816(acc[1][ni], A1, B + ni*2);
        }
      }
    }
    if (more){
      sts128(dbuf + oB, fB);
      CP_WAIT0();
      __syncthreads();
    }
  }

  // ---- epilogue: vector scatter-add into out[token, h] ----
  if (mact){
    const int g = lane >> 2, c = lane & 3;
    #pragma unroll
    for (int mi = 0; mi < 2; mi++){
      #pragma unroll
      for (int h = 0; h < 2; h++){
        int R = mw*32 + mi*16 + g + 8*h;
        int p = row0 + R;
        if (p < pend){
          int tok = g_perm[p];
          float* orow = out + (size_t)tok*HD + h0 + nw*64 + 2*c;
          #pragma unroll
          for (int ni = 0; ni < 8; ni++){
            red2(orow + ni*8, acc[mi][ni][2*h], acc[mi][ni][2*h+1]);
          }
        }
      }
    }
  }
}

// ---------------- launch ----------------
extern "C" void kernel_launch(void* const* d_in, const int* in_sizes, int n_in,
                              void* d_out, int out_size)
{
  const float* X  = (const float*)d_in[0];
  const int*   ix = (const int*)d_in[1];
  const float* tw = (const float*)d_in[2];
  const float* GU = (const float*)d_in[3];
  const float* DW = (const float*)d_in[4];
  float* out = (float*)d_out;
  (void)in_sizes; (void)n_in; (void)out_size;

  cudaFuncSetAttribute(gemm1_kernel, cudaFuncAttributeMaxDynamicSharedMemorySize, G1_SMEM);
  cudaFuncSetAttribute(gemm2_kernel, cudaFuncAttributeMaxDynamicSharedMemorySize, G2_SMEM);

  prep_kernel<<<(NTOK*HD/2 + 255)/256, 256>>>(X, (float4*)out);
  route_kernel<<<1, 256>>>(ix, tw);
  gemm1_kernel<<<dim3(MAXMT, ID/64),  512, G1_SMEM>>>(GU);
  gemm2_kernel<<<dim3(MAXMT, HD/128), 512, G2_SMEM>>>(DW, out);
}

// round 16
// speedup vs baseline: 1.0243x; 1.0243x over previous
#include <cuda_runtime.h>
#include <cuda_fp16.h>
#include <cstdint>
#include <math.h>

// Problem sizes (fixed)
#define NE   32
#define HD   2048
#define ID   1536
#define NTOK 1024
#define TOPK 8
#define NP   (NTOK*TOPK)
#define BM   128
#define MAXMT 96

// ---------------- device scratch ----------------
__device__ int    g_perm[NP];
__device__ float  g_pw[NP];
__device__ int    g_off[NE+1];
__device__ int    g_mt_e[MAXMT];
__device__ int    g_mt_r[MAXMT];
__device__ int    g_mt_n[MAXMT];          // tile m-rows (32..128, mult of 32)
__device__ int    g_nmt;
__device__ __half g_xh[(size_t)NTOK*HD];  // 4 MB fp16 hidden states
__device__ __half g_act[(size_t)NP*ID];   // 24 MB fp16 activations

// ---------------- helpers ----------------
__device__ __forceinline__ uint32_t smem_u32(const void* p){
  uint32_t a;
  asm("{ .reg .u64 t; cvta.to.shared.u64 t, %1; cvt.u32.u64 %0, t; }" : "=r"(a) : "l"(p));
  return a;
}
__device__ __forceinline__ uint32_t f22h(float lo, float hi){
  uint32_t r; asm("cvt.rn.f16x2.f32 %0, %1, %2;" : "=r"(r) : "f"(hi), "f"(lo));
  return r;
}
__device__ __forceinline__ void ldsm4(uint32_t* r, uint32_t a){
  asm volatile("ldmatrix.sync.aligned.m8n8.x4.shared.b16 {%0,%1,%2,%3}, [%4];"
    : "=r"(r[0]),"=r"(r[1]),"=r"(r[2]),"=r"(r[3]) : "r"(a));
}
__device__ __forceinline__ void sts128(uint32_t a, uint4 v){
  asm volatile("st.shared.v4.b32 [%0], {%1,%2,%3,%4};"
    :: "r"(a), "r"(v.x), "r"(v.y), "r"(v.z), "r"(v.w));
}
__device__ __forceinline__ void cpasync16(uint32_t dst, const void* src){
  asm volatile("cp.async.cg.shared.global [%0], [%1], 16;" :: "r"(dst), "l"(src));
}
#define CP_COMMIT() asm volatile("cp.async.commit_group;" ::: "memory")
#define CP_WAIT0()  asm volatile("cp.async.wait_group 0;" ::: "memory")
__device__ __forceinline__ void mma16816(float* d, const uint32_t* a, const uint32_t* b){
  asm volatile(
    "mma.sync.aligned.m16n8k16.row.col.f32.f16.f16.f32 "
    "{%0,%1,%2,%3},{%4,%5,%6,%7},{%8,%9},{%0,%1,%2,%3};"
    : "+f"(d[0]),"+f"(d[1]),"+f"(d[2]),"+f"(d[3])
    : "r"(a[0]),"r"(a[1]),"r"(a[2]),"r"(a[3]), "r"(b[0]),"r"(b[1]));
}
__device__ __forceinline__ void red2(float* p, float x, float y){
  asm volatile("red.global.add.v2.f32 [%0], {%1,%2};" :: "l"(p), "f"(x), "f"(y) : "memory");
}
// 64B-pitch swizzle (32 fp16 per row), for gemm2
__device__ __forceinline__ uint32_t swz(uint32_t r){
  return (r << 6) ^ (((r >> 1) & 3u) << 4);
}
// 128B-pitch swizzle (64 fp16 per row), for gemm1
__device__ __forceinline__ uint32_t swz128(uint32_t r, uint32_t cb){
  return (r << 7) + (((cb ^ (r & 7u))) << 4);
}
__device__ __forceinline__ uint4 pk(const float4 a, const float4 b){
  uint4 r; r.x = f22h(a.x,a.y); r.y = f22h(a.z,a.w);
  r.z = f22h(b.x,b.y); r.w = f22h(b.z,b.w);
  return r;
}
// load 8 fp32 -> 16B fp16
__device__ __forceinline__ uint4 ld8cvt(const float* s){
  float4 u = *(const float4*)s; float4 v = *(const float4*)(s+4);
  uint4 r; r.x = f22h(u.x,u.y); r.y = f22h(u.z,u.w);
  r.z = f22h(v.x,v.y); r.w = f22h(v.z,v.w);
  return r;
}

// ---------------- small kernels ----------------
// prep: zero output + convert X to fp16 (merged, one launch)
__global__ void prep_kernel(const float* __restrict__ X, float4* __restrict__ out){
  int i = blockIdx.x*256 + threadIdx.x;
  if (i < NTOK*HD/2){
    float2 v = ((const float2*)X)[i];
    ((uint32_t*)g_xh)[i] = f22h(v.x, v.y);
  }
  if (i < NTOK*HD/4) out[i] = make_float4(0.f,0.f,0.f,0.f);
}

__global__ void route_kernel(const int* __restrict__ idx, const float* __restrict__ w){
  __shared__ int cnt[NE];
  __shared__ int cur[NE];
  __shared__ int soff[NE+1];
  int tid = threadIdx.x;
  if (tid < NE) cnt[tid] = 0;
  __syncthreads();
  for (int i = tid; i < NP; i += blockDim.x) atomicAdd(&cnt[idx[i]], 1);
  __syncthreads();
  if (tid == 0){
    int s = 0, nm = 0;
    for (int e = 0; e < NE; e++){
      soff[e] = s;
      for (int j = 0; j < cnt[e]; j += BM){
        int rem = cnt[e] - j;
        int sz  = (rem >= BM) ? BM : ((rem + 31) & ~31);
        g_mt_e[nm] = e; g_mt_r[nm] = s + j; g_mt_n[nm] = sz; nm++;
      }
      s += cnt[e];
    }
    soff[NE] = s;
    g_nmt = nm;
  }
  __syncthreads();
  if (tid <= NE) g_off[tid] = soff[tid];
  if (tid <  NE) cur[tid]  = soff[tid];
  __syncthreads();
  for (int i = tid; i < NP; i += blockDim.x){
    int e = idx[i];
    int p = atomicAdd(&cur[e], 1);
    g_perm[p] = i / TOPK;
    g_pw[p]   = w[i];
  }
}

// =================== GEMM1 ===================
// Block <=128 tokens x 64 inter-channels (gate+up). BK=64 per stage.
// Stage: A [0,16K), G [16K,24K), U [24K,32K). 2 stages = 64KB.
// 256 thr (8 warps = 4m x 2n), 2 CTAs/SM. Warp tile 32m x 32ch dual.
#define G1_STAGE 32768
#define G1_SMEM  65536
#define G1_NKT   (HD/64)   // 32

__global__ __launch_bounds__(256,2) void gemm1_kernel(const float* __restrict__ GU)
{
  const int mt = blockIdx.x;
  if (mt >= g_nmt) return;
  const int e = g_mt_e[mt], row0 = g_mt_r[mt], pend = g_off[e+1];
  const int mrows = g_mt_n[mt];
  const int i0 = blockIdx.y * 64;

  extern __shared__ char smem[];
  const uint32_t sb = smem_u32(smem);
  const int t = threadIdx.x, lane = t & 31, wid = t >> 5;
  const int mw = wid & 3, nw = wid >> 2;       // 4m x 2n warps
  const bool mact = (mw*32 < mrows);           // warp has live m-rows

  // ---- producer A: 2 thr/row, 128 rows, 64B per thread (4 x 16B) ----
  const int lrA = t >> 1, qA = t & 1;
  const bool aact = (lrA < mrows);
  int pa = row0 + lrA; int pc = (pa < pend) ? pa : row0;
  const __half* srcA = g_xh + (size_t)g_perm[pc]*HD + qA*32;
  uint32_t oA[4];
  #pragma unroll
  for (int j = 0; j < 4; j++) oA[j] = swz128(lrA, 4*qA + j);

  // ---- producer G/U: 4 thr/row, 64 rows, 16 fp32 per thread ----
  const int lrB = t >> 2, qB = t & 3;
  const float* gu_e = GU + (size_t)e*(2*ID)*HD;
  const float* srcG = gu_e + (size_t)(i0 + lrB)*HD + qB*16;
  const float* srcU = gu_e + (size_t)(ID + i0 + lrB)*HD + qB*16;
  const uint32_t oG0 = 16384 + swz128(lrB, 2*qB), oG1 = 16384 + swz128(lrB, 2*qB+1);
  const uint32_t oU0 = oG0 + 8192, oU1 = oG1 + 8192;

  // ---- consumer fragment bases ----
  const uint32_t hi = lane >> 4;
  const uint32_t r0 = mw*32 + (lane & 15), r1 = r0 + 16;
  const uint32_t a0b = r0 << 7, a0x = r0 & 7;
  const uint32_t a1b = r1 << 7, a1x = r1 & 7;
  const int brl = (lane & 7) + (((lane >> 4) & 1) << 3);
  const uint32_t bh = (lane >> 3) & 1;
  const uint32_t rg0 = nw*32 + brl, rg1 = rg0 + 16;
  const uint32_t g0b = 16384 + (rg0 << 7), g0x = rg0 & 7;
  const uint32_t g1b = 16384 + (rg1 << 7), g1x = rg1 & 7;

  float accg[2][4][4] = {}, accu[2][4][4] = {};

  // ---- prologue: fill stage 0 ----
  {
    if (aact){
      #pragma unroll
      for (int j = 0; j < 4; j++) cpasync16(sb + oA[j], srcA + j*8);
    }
    CP_COMMIT();
    float4 a0 = *(const float4*)(srcG),    a1 = *(const float4*)(srcG+4);
    float4 a2 = *(const float4*)(srcG+8),  a3 = *(const float4*)(srcG+12);
    sts128(sb + oG0, pk(a0,a1)); sts128(sb + oG1, pk(a2,a3));
    float4 u0 = *(const float4*)(srcU),    u1 = *(const float4*)(srcU+4);
    float4 u2 = *(const float4*)(srcU+8),  u3 = *(const float4*)(srcU+12);
    sts128(sb + oU0, pk(u0,u1)); sts128(sb + oU1, pk(u2,u3));
    CP_WAIT0();
  }
  __syncthreads();

  for (int kt = 0; kt < G1_NKT; kt++){
    const uint32_t cur = sb + (uint32_t)(kt & 1)*G1_STAGE;
    const uint32_t nxt = sb + (uint32_t)((kt + 1) & 1)*G1_STAGE;
    const bool more = (kt + 1 < G1_NKT);
    const int ko = (kt + 1)*64;

    float4 fg[4];
    if (more){
      if (aact){
        #pragma unroll
        for (int j = 0; j < 4; j++) cpasync16(nxt + oA[j], srcA + ko + j*8);
      }
      CP_COMMIT();
      const float* sg = srcG + ko;
      fg[0] = *(const float4*)sg;     fg[1] = *(const float4*)(sg+4);
      fg[2] = *(const float4*)(sg+8); fg[3] = *(const float4*)(sg+12);
    }
    // ks 0,1 (rotated per m-warp to desynchronize LDSM bursts)
    if (mact){
      #pragma unroll
      for (int ks = 0; ks < 2; ks++){
        const uint32_t ksr = (uint32_t)((ks + mw) & 3);
        const uint32_t cbA = 2*ksr + hi, cbB = 2*ksr + bh;
        uint32_t A0[4], A1[4], Bg[8], Bu[8];
        ldsm4(A0,   cur + a0b + ((cbA ^ a0x) << 4));
        ldsm4(A1,   cur + a1b + ((cbA ^ a1x) << 4));
        ldsm4(Bg,   cur + g0b + ((cbB ^ g0x) << 4));
        ldsm4(Bg+4, cur + g1b + ((cbB ^ g1x) << 4));
        ldsm4(Bu,   cur + g0b + 8192 + ((cbB ^ g0x) << 4));
        ldsm4(Bu+4, cur + g1b + 8192 + ((cbB ^ g1x) << 4));
        #pragma unroll
        for (int ni = 0; ni < 4; ni++){
          mma16816(accg[0][ni], A0, Bg + ni*2);
          mma16816(accg[1][ni], A1, Bg + ni*2);
          mma16816(accu[0][ni], A0, Bu + ni*2);
          mma16816(accu[1][ni], A1, Bu + ni*2);
        }
      }
    }
    float4 fu[4];
    if (more){
      sts128(nxt + oG0, pk(fg[0],fg[1]));
      sts128(nxt + oG1, pk(fg[2],fg[3]));
      const float* su = srcU + ko;
      fu[0] = *(const float4*)su;     fu[1] = *(const float4*)(su+4);
      fu[2] = *(const float4*)(su+8); fu[3] = *(const float4*)(su+12);
    }
    // ks 2,3
    if (mact){
      #pragma unroll
      for (int ks = 2; ks < 4; ks++){
        const uint32_t ksr = (uint32_t)((ks + mw) & 3);
        const uint32_t cbA = 2*ksr + hi, cbB = 2*ksr + bh;
        uint32_t A0[4], A1[4], Bg[8], Bu[8];
        ldsm4(A0,   cur + a0b + ((cbA ^ a0x) << 4));
        ldsm4(A1,   cur + a1b + ((cbA ^ a1x) << 4));
        ldsm4(Bg,   cur + g0b + ((cbB ^ g0x) << 4));
        ldsm4(Bg+4, cur + g1b + ((cbB ^ g1x) << 4));
        ldsm4(Bu,   cur + g0b + 8192 + ((cbB ^ g0x) << 4));
        ldsm4(Bu+4, cur + g1b + 8192 + ((cbB ^ g1x) << 4));
        #pragma unroll
        for (int ni = 0; ni < 4; ni++){
          mma16816(accg[0][ni], A0, Bg + ni*2);
          mma16816(accg[1][ni], A1, Bg + ni*2);
          mma16816(accu[0][ni], A0, Bu + ni*2);
          mma16816(accu[1][ni], A1, Bu + ni*2);
        }
      }
    }
    if (more){
      sts128(nxt + oU0, pk(fu[0],fu[1]));
      sts128(nxt + oU1, pk(fu[2],fu[3]));
      CP_WAIT0();
      __syncthreads();
    }
  }

  // ---- epilogue: silu(gate)*up*router_weight -> g_act fp16 ----
  if (mact){
    const int g = lane >> 2, c = lane & 3;
    #pragma unroll
    for (int mi = 0; mi < 2; mi++){
      #pragma unroll
      for (int h = 0; h < 2; h++){
        int R = mw*32 + mi*16 + g + 8*h;
        int p = row0 + R;
        if (p < pend){
          float wgt = g_pw[p];
          __half* arow = g_act + (size_t)p*ID + i0 + nw*32 + 2*c;
          #pragma unroll
          for (int ni = 0; ni < 4; ni++){
            float gv0 = accg[mi][ni][2*h],   gv1 = accg[mi][ni][2*h+1];
            float uv0 = accu[mi][ni][2*h],   uv1 = accu[mi][ni][2*h+1];
            float o0 = wgt * (gv0 / (1.f + __expf(-gv0))) * uv0;
            float o1 = wgt * (gv1 / (1.f + __expf(-gv1))) * uv1;
            *(__half2*)(arow + ni*8) = __floats2half2_rn(o0, o1);
          }
        }
      }
    }
  }
}

// =================== GEMM2 ===================
// Block <=128 act-rows x 128 h-channels. BK=32, double buffer 16KB stages.
// 256 thr (8 warps = 4m x 2n), 2 CTAs/SM. Warp tile 32m x 64n.
#define G2_STAGE 16384
#define G2_SMEM  32768
#define G2_NKT   (ID/32)   // 48

__global__ __launch_bounds__(256,2) void gemm2_kernel(const float* __restrict__ DW,
                                                      float* __restrict__ out)
{
  const int mt = blockIdx.x;
  if (mt >= g_nmt) return;
  const int e = g_mt_e[mt], row0 = g_mt_r[mt], pend = g_off[e+1];
  const int mrows = g_mt_n[mt];
  const int h0 = blockIdx.y * 128;

  extern __shared__ char smem[];
  const uint32_t sb = smem_u32(smem);
  const int t = threadIdx.x, lane = t & 31, wid = t >> 5;
  const int mw = wid & 3, nw = wid >> 2;       // 4m x 2n warps (32m x 64n each)
  const bool mact = (mw*32 < mrows);

  // ---- producer: 4 threads/row; A 128 rows (2 passes), B 128 rows (2 passes)
  // NOTE: g_act is indexed by grouped row p directly (NO g_perm)
  const int lr = t >> 2, q = t & 3;
  const __half* srcA[2];
  const float*  srcB[2];
  uint32_t sAo[2], sBo[2];
  bool av[2];
  const float* dw_e = DW + (size_t)e*HD*ID;
  #pragma unroll
  for (int j = 0; j < 2; j++){
    int r = lr + j*64;
    av[j] = (r < mrows);
    int p = row0 + r; int pcl = (p < pend) ? p : row0;
    srcA[j] = g_act + (size_t)pcl*ID + q*8;
    srcB[j] = dw_e + (size_t)(h0 + r)*ID + q*8;
    sAo[j] = swz(r) ^ (q << 4);
    sBo[j] = sAo[j] + 8192;
  }

  // ---- consumer fragment offsets ----
  const uint32_t ca = (uint32_t)(lane >> 4) << 4;
  const uint32_t pa0 = swz(mw*32 + (lane & 15)) ^ ca;
  const uint32_t pa1 = swz(mw*32 + 16 + (lane & 15)) ^ ca;
  const int brl = (lane & 7) + (((lane >> 4) & 1) << 3);
  const uint32_t cb = (uint32_t)((lane >> 3) & 1) << 4;
  uint32_t pb[4];
  #pragma unroll
  for (int j = 0; j < 4; j++)
    pb[j] = swz(128 + nw*64 + j*16 + brl) ^ cb;

  float acc[2][8][4] = {};

  // preload
  if (av[0]) sts128(sb + sAo[0], *(const uint4*)srcA[0]);
  if (av[1]) sts128(sb + sAo[1], *(const uint4*)srcA[1]);
  sts128(sb + sBo[0], ld8cvt(srcB[0]));
  sts128(sb + sBo[1], ld8cvt(srcB[1]));
  __syncthreads();

  for (int kt = 0; kt < G2_NKT; kt++){
    const uint32_t sbuf = sb + (uint32_t)(kt & 1)*G2_STAGE;
    uint4 fA0, fA1, fB0, fB1;
    if (kt + 1 < G2_NKT){
      const int ko = (kt + 1)*32;
      if (av[0]) fA0 = *(const uint4*)(srcA[0] + ko);
      if (av[1]) fA1 = *(const uint4*)(srcA[1] + ko);
      fB0 = ld8cvt(srcB[0] + ko);
      fB1 = ld8cvt(srcB[1] + ko);
    }
    if (mact){
      #pragma unroll
      for (int ks = 0; ks < 2; ks++){
        const uint32_t k5 = ((uint32_t)((ks + wid) & 1)) << 5;   // rotated
        uint32_t A0[4], A1[4], B[16];
        ldsm4(A0, sbuf + (pa0 ^ k5));
        ldsm4(A1, sbuf + (pa1 ^ k5));
        #pragma unroll
        for (int j = 0; j < 4; j++) ldsm4(B + j*4, sbuf + (pb[j] ^ k5));
        #pragma unroll
        for (int ni = 0; ni < 8; ni++){
          mma16816(acc[0][ni], A0, B + ni*2);
          mma16816(acc[1][ni], A1, B + ni*2);
        }
      }
    }
    if (kt + 1 < G2_NKT){
      const uint32_t dbuf = sb + (uint32_t)((kt + 1) & 1)*G2_STAGE;
      if (av[0]) sts128(dbuf + sAo[0], fA0);
      if (av[1]) sts128(dbuf + sAo[1], fA1);
      sts128(dbuf + sBo[0], fB0); sts128(dbuf + sBo[1], fB1);
      __syncthreads();
    }
  }

  // ---- epilogue: vector scatter-add into out[token, h] ----
  if (mact){
    const int g = lane >> 2, c = lane & 3;
    #pragma unroll
    for (int mi = 0; mi < 2; mi++){
      #pragma unroll
      for (int h = 0; h < 2; h++){
        int R = mw*32 + mi*16 + g + 8*h;
        int p = row0 + R;
        if (p < pend){
          int tok = g_perm[p];
          float* orow = out + (size_t)tok*HD + h0 + nw*64 + 2*c;
          #pragma unroll
          for (int ni = 0; ni < 8; ni++){
            red2(orow + ni*8, acc[mi][ni][2*h], acc[mi][ni][2*h+1]);
          }
        }
      }
    }
  }
}

// ---------------- launch ----------------
extern "C" void kernel_launch(void* const* d_in, const int* in_sizes, int n_in,
                              void* d_out, int out_size)
{
  const float* X  = (const float*)d_in[0];
  const int*   ix = (const int*)d_in[1];
  const float* tw = (const float*)d_in[2];
  const float* GU = (const float*)d_in[3];
  const float* DW = (const float*)d_in[4];
  float* out = (float*)d_out;
  (void)in_sizes; (void)n_in; (void)out_size;

  cudaFuncSetAttribute(gemm1_kernel, cudaFuncAttributeMaxDynamicSharedMemorySize, G1_SMEM);
  cudaFuncSetAttribute(gemm2_kernel, cudaFuncAttributeMaxDynamicSharedMemorySize, G2_SMEM);

  prep_kernel<<<(NTOK*HD/2 + 255)/256, 256>>>(X, (float4*)out);
  route_kernel<<<1, 256>>>(ix, tw);
  gemm1_kernel<<<dim3(MAXMT, ID/64),  256, G1_SMEM>>>(GU);
  gemm2_kernel<<<dim3(MAXMT, HD/128), 256, G2_SMEM>>>(DW, out);
}

// round 17
// speedup vs baseline: 1.0269x; 1.0025x over previous
#include <cuda_runtime.h>
#include <cuda_fp16.h>
#include <cstdint>
#include <math.h>

// Problem sizes (fixed)
#define NE   32
#define HD   2048
#define ID   1536
#define NTOK 1024
#define TOPK 8
#define NP   (NTOK*TOPK)
#define BM   128
#define MAXMT 96

// ---------------- device scratch ----------------
__device__ int    g_perm[NP];
__device__ float  g_pw[NP];
__device__ int    g_off[NE+1];
__device__ int    g_mt_e[MAXMT];
__device__ int    g_mt_r[MAXMT];
__device__ int    g_mt_n[MAXMT];          // tile m-rows (32..128, mult of 32)
__device__ int    g_nmt;
__device__ __half g_xh[(size_t)NTOK*HD];  // 4 MB fp16 hidden states
__device__ __half g_act[(size_t)NP*ID];   // 24 MB fp16 activations

// ---------------- helpers ----------------
__device__ __forceinline__ uint32_t smem_u32(const void* p){
  uint32_t a;
  asm("{ .reg .u64 t; cvta.to.shared.u64 t, %1; cvt.u32.u64 %0, t; }" : "=r"(a) : "l"(p));
  return a;
}
__device__ __forceinline__ uint32_t f22h(float lo, float hi){
  uint32_t r; asm("cvt.rn.f16x2.f32 %0, %1, %2;" : "=r"(r) : "f"(hi), "f"(lo));
  return r;
}
__device__ __forceinline__ void ldsm4(uint32_t* r, uint32_t a){
  asm volatile("ldmatrix.sync.aligned.m8n8.x4.shared.b16 {%0,%1,%2,%3}, [%4];"
    : "=r"(r[0]),"=r"(r[1]),"=r"(r[2]),"=r"(r[3]) : "r"(a));
}
__device__ __forceinline__ void sts128(uint32_t a, uint4 v){
  asm volatile("st.shared.v4.b32 [%0], {%1,%2,%3,%4};"
    :: "r"(a), "r"(v.x), "r"(v.y), "r"(v.z), "r"(v.w));
}
__device__ __forceinline__ void cpasync16(uint32_t dst, const void* src){
  asm volatile("cp.async.cg.shared.global [%0], [%1], 16;" :: "r"(dst), "l"(src));
}
#define CP_COMMIT() asm volatile("cp.async.commit_group;" ::: "memory")
#define CP_WAIT0()  asm volatile("cp.async.wait_group 0;" ::: "memory")
__device__ __forceinline__ void mma16816(float* d, const uint32_t* a, const uint32_t* b){
  asm volatile(
    "mma.sync.aligned.m16n8k16.row.col.f32.f16.f16.f32 "
    "{%0,%1,%2,%3},{%4,%5,%6,%7},{%8,%9},{%0,%1,%2,%3};"
    : "+f"(d[0]),"+f"(d[1]),"+f"(d[2]),"+f"(d[3])
    : "r"(a[0]),"r"(a[1]),"r"(a[2]),"r"(a[3]), "r"(b[0]),"r"(b[1]));
}
__device__ __forceinline__ void red2(float* p, float x, float y){
  asm volatile("red.global.add.v2.f32 [%0], {%1,%2};" :: "l"(p), "f"(x), "f"(y) : "memory");
}
// 64B-pitch swizzle (32 fp16 per row), for gemm2
__device__ __forceinline__ uint32_t swz(uint32_t r){
  return (r << 6) ^ (((r >> 1) & 3u) << 4);
}
// 128B-pitch swizzle (64 fp16 per row), for gemm1
__device__ __forceinline__ uint32_t swz128(uint32_t r, uint32_t cb){
  return (r << 7) + (((cb ^ (r & 7u))) << 4);
}
__device__ __forceinline__ uint4 pk(const float4 a, const float4 b){
  uint4 r; r.x = f22h(a.x,a.y); r.y = f22h(a.z,a.w);
  r.z = f22h(b.x,b.y); r.w = f22h(b.z,b.w);
  return r;
}
// load 8 fp32 -> 16B fp16
__device__ __forceinline__ uint4 ld8cvt(const float* s){
  float4 u = *(const float4*)s; float4 v = *(const float4*)(s+4);
  uint4 r; r.x = f22h(u.x,u.y); r.y = f22h(u.z,u.w);
  r.z = f22h(v.x,v.y); r.w = f22h(v.z,v.w);
  return r;
}

// ---------------- prep+route (merged, one launch) ----------------
// Blocks [0, NB-1): zero output + convert X to fp16.
// Block NB-1: build routing tables (independent of the other blocks' work).
#define PREP_NB ((NTOK*HD/2 + 255)/256 + 1)

__global__ void prep_kernel(const float* __restrict__ X, float4* __restrict__ out,
                            const int* __restrict__ idx, const float* __restrict__ w)
{
  if (blockIdx.x < PREP_NB - 1){
    int i = blockIdx.x*256 + threadIdx.x;
    if (i < NTOK*HD/2){
      float2 v = ((const float2*)X)[i];
      ((uint32_t*)g_xh)[i] = f22h(v.x, v.y);
    }
    if (i < NTOK*HD/4) out[i] = make_float4(0.f,0.f,0.f,0.f);
    return;
  }
  // ---- routing block ----
  __shared__ int cnt[NE];
  __shared__ int cur[NE];
  __shared__ int soff[NE+1];
  int tid = threadIdx.x;
  if (tid < NE) cnt[tid] = 0;
  __syncthreads();
  for (int i = tid; i < NP; i += blockDim.x) atomicAdd(&cnt[idx[i]], 1);
  __syncthreads();
  if (tid == 0){
    int s = 0, nm = 0;
    for (int e = 0; e < NE; e++){
      soff[e] = s;
      for (int j = 0; j < cnt[e]; j += BM){
        int rem = cnt[e] - j;
        int sz  = (rem >= BM) ? BM : ((rem + 31) & ~31);
        g_mt_e[nm] = e; g_mt_r[nm] = s + j; g_mt_n[nm] = sz; nm++;
      }
      s += cnt[e];
    }
    soff[NE] = s;
    g_nmt = nm;
  }
  __syncthreads();
  if (tid <= NE) g_off[tid] = soff[tid];
  if (tid <  NE) cur[tid]  = soff[tid];
  __syncthreads();
  for (int i = tid; i < NP; i += blockDim.x){
    int e = idx[i];
    int p = atomicAdd(&cur[e], 1);
    g_perm[p] = i / TOPK;
    g_pw[p]   = w[i];
  }
}

// =================== GEMM1 ===================
// Block <=128 tokens x 64 inter-channels (gate+up). BK=64 per stage.
// Stage: A [0,16K), G [16K,24K), U [24K,32K). 2 stages = 64KB.
// 256 thr (8 warps = 4m x 2n), 2 CTAs/SM. Warp tile 32m x 32ch dual.
#define G1_STAGE 32768
#define G1_SMEM  65536
#define G1_NKT   (HD/64)   // 32

__global__ __launch_bounds__(256,2) void gemm1_kernel(const float* __restrict__ GU)
{
  const int mt = blockIdx.x;
  if (mt >= g_nmt) return;
  const int e = g_mt_e[mt], row0 = g_mt_r[mt], pend = g_off[e+1];
  const int mrows = g_mt_n[mt];
  const int i0 = blockIdx.y * 64;

  extern __shared__ char smem[];
  const uint32_t sb = smem_u32(smem);
  const int t = threadIdx.x, lane = t & 31, wid = t >> 5;
  const int mw = wid & 3, nw = wid >> 2;       // 4m x 2n warps
  const bool mact = (mw*32 < mrows);           // warp has live m-rows

  // ---- producer A: 2 thr/row, 128 rows, 64B per thread (4 x 16B) ----
  const int lrA = t >> 1, qA = t & 1;
  const bool aact = (lrA < mrows);
  int pa = row0 + lrA; int pc = (pa < pend) ? pa : row0;
  const __half* srcA = g_xh + (size_t)g_perm[pc]*HD + qA*32;
  uint32_t oA[4];
  #pragma unroll
  for (int j = 0; j < 4; j++) oA[j] = swz128(lrA, 4*qA + j);

  // ---- producer G/U: 4 thr/row, 64 rows, 16 fp32 per thread ----
  const int lrB = t >> 2, qB = t & 3;
  const float* gu_e = GU + (size_t)e*(2*ID)*HD;
  const float* srcG = gu_e + (size_t)(i0 + lrB)*HD + qB*16;
  const float* srcU = gu_e + (size_t)(ID + i0 + lrB)*HD + qB*16;
  const uint32_t oG0 = 16384 + swz128(lrB, 2*qB), oG1 = 16384 + swz128(lrB, 2*qB+1);
  const uint32_t oU0 = oG0 + 8192, oU1 = oG1 + 8192;

  // ---- consumer fragment bases ----
  const uint32_t hi = lane >> 4;
  const uint32_t r0 = mw*32 + (lane & 15), r1 = r0 + 16;
  const uint32_t a0b = r0 << 7, a0x = r0 & 7;
  const uint32_t a1b = r1 << 7, a1x = r1 & 7;
  const int brl = (lane & 7) + (((lane >> 4) & 1) << 3);
  const uint32_t bh = (lane >> 3) & 1;
  const uint32_t rg0 = nw*32 + brl, rg1 = rg0 + 16;
  const uint32_t g0b = 16384 + (rg0 << 7), g0x = rg0 & 7;
  const uint32_t g1b = 16384 + (rg1 << 7), g1x = rg1 & 7;

  float accg[2][4][4] = {}, accu[2][4][4] = {};

  // ---- prologue: fill stage 0 ----
  {
    if (aact){
      #pragma unroll
      for (int j = 0; j < 4; j++) cpasync16(sb + oA[j], srcA + j*8);
    }
    CP_COMMIT();
    float4 a0 = *(const float4*)(srcG),    a1 = *(const float4*)(srcG+4);
    float4 a2 = *(const float4*)(srcG+8),  a3 = *(const float4*)(srcG+12);
    sts128(sb + oG0, pk(a0,a1)); sts128(sb + oG1, pk(a2,a3));
    float4 u0 = *(const float4*)(srcU),    u1 = *(const float4*)(srcU+4);
    float4 u2 = *(const float4*)(srcU+8),  u3 = *(const float4*)(srcU+12);
    sts128(sb + oU0, pk(u0,u1)); sts128(sb + oU1, pk(u2,u3));
    CP_WAIT0();
  }
  __syncthreads();

  for (int kt = 0; kt < G1_NKT; kt++){
    const uint32_t cur = sb + (uint32_t)(kt & 1)*G1_STAGE;
    const uint32_t nxt = sb + (uint32_t)((kt + 1) & 1)*G1_STAGE;
    const bool more = (kt + 1 < G1_NKT);
    const int ko = (kt + 1)*64;

    float4 fg[4];
    if (more){
      if (aact){
        #pragma unroll
        for (int j = 0; j < 4; j++) cpasync16(nxt + oA[j], srcA + ko + j*8);
      }
      CP_COMMIT();
      const float* sg = srcG + ko;
      fg[0] = *(const float4*)sg;     fg[1] = *(const float4*)(sg+4);
      fg[2] = *(const float4*)(sg+8); fg[3] = *(const float4*)(sg+12);
    }
    // ks 0,1 (rotated per m-warp to desynchronize LDSM bursts)
    if (mact){
      #pragma unroll
      for (int ks = 0; ks < 2; ks++){
        const uint32_t ksr = (uint32_t)((ks + mw) & 3);
        const uint32_t cbA = 2*ksr + hi, cbB = 2*ksr + bh;
        uint32_t A0[4], A1[4], Bg[8], Bu[8];
        ldsm4(A0,   cur + a0b + ((cbA ^ a0x) << 4));
        ldsm4(A1,   cur + a1b + ((cbA ^ a1x) << 4));
        ldsm4(Bg,   cur + g0b + ((cbB ^ g0x) << 4));
        ldsm4(Bg+4, cur + g1b + ((cbB ^ g1x) << 4));
        ldsm4(Bu,   cur + g0b + 8192 + ((cbB ^ g0x) << 4));
        ldsm4(Bu+4, cur + g1b + 8192 + ((cbB ^ g1x) << 4));
        #pragma unroll
        for (int ni = 0; ni < 4; ni++){
          mma16816(accg[0][ni], A0, Bg + ni*2);
          mma16816(accg[1][ni], A1, Bg + ni*2);
          mma16816(accu[0][ni], A0, Bu + ni*2);
          mma16816(accu[1][ni], A1, Bu + ni*2);
        }
      }
    }
    float4 fu[4];
    if (more){
      sts128(nxt + oG0, pk(fg[0],fg[1]));
      sts128(nxt + oG1, pk(fg[2],fg[3]));
      const float* su = srcU + ko;
      fu[0] = *(const float4*)su;     fu[1] = *(const float4*)(su+4);
      fu[2] = *(const float4*)(su+8); fu[3] = *(const float4*)(su+12);
    }
    // ks 2,3
    if (mact){
      #pragma unroll
      for (int ks = 2; ks < 4; ks++){
        const uint32_t ksr = (uint32_t)((ks + mw) & 3);
        const uint32_t cbA = 2*ksr + hi, cbB = 2*ksr + bh;
        uint32_t A0[4], A1[4], Bg[8], Bu[8];
        ldsm4(A0,   cur + a0b + ((cbA ^ a0x) << 4));
        ldsm4(A1,   cur + a1b + ((cbA ^ a1x) << 4));
        ldsm4(Bg,   cur + g0b + ((cbB ^ g0x) << 4));
        ldsm4(Bg+4, cur + g1b + ((cbB ^ g1x) << 4));
        ldsm4(Bu,   cur + g0b + 8192 + ((cbB ^ g0x) << 4));
        ldsm4(Bu+4, cur + g1b + 8192 + ((cbB ^ g1x) << 4));
        #pragma unroll
        for (int ni = 0; ni < 4; ni++){
          mma16816(accg[0][ni], A0, Bg + ni*2);
          mma16816(accg[1][ni], A1, Bg + ni*2);
          mma16816(accu[0][ni], A0, Bu + ni*2);
          mma16816(accu[1][ni], A1, Bu + ni*2);
        }
      }
    }
    if (more){
      sts128(nxt + oU0, pk(fu[0],fu[1]));
      sts128(nxt + oU1, pk(fu[2],fu[3]));
      CP_WAIT0();
      __syncthreads();
    }
  }

  // ---- epilogue: silu(gate)*up*router_weight -> g_act fp16 ----
  if (mact){
    const int g = lane >> 2, c = lane & 3;
    #pragma unroll
    for (int mi = 0; mi < 2; mi++){
      #pragma unroll
      for (int h = 0; h < 2; h++){
        int R = mw*32 + mi*16 + g + 8*h;
        int p = row0 + R;
        if (p < pend){
          float wgt = g_pw[p];
          __half* arow = g_act + (size_t)p*ID + i0 + nw*32 + 2*c;
          #pragma unroll
          for (int ni = 0; ni < 4; ni++){
            float gv0 = accg[mi][ni][2*h],   gv1 = accg[mi][ni][2*h+1];
            float uv0 = accu[mi][ni][2*h],   uv1 = accu[mi][ni][2*h+1];
            float o0 = wgt * (gv0 / (1.f + __expf(-gv0))) * uv0;
            float o1 = wgt * (gv1 / (1.f + __expf(-gv1))) * uv1;
            *(__half2*)(arow + ni*8) = __floats2half2_rn(o0, o1);
          }
        }
      }
    }
  }
}

// =================== GEMM2 ===================
// Block <=128 act-rows x 128 h-channels. BK=32, double buffer 16KB stages.
// 256 thr (8 warps = 4m x 2n), 2 CTAs/SM. Warp tile 32m x 64n.
#define G2_STAGE 16384
#define G2_SMEM  32768
#define G2_NKT   (ID/32)   // 48

__global__ __launch_bounds__(256,2) void gemm2_kernel(const float* __restrict__ DW,
                                                      float* __restrict__ out)
{
  const int mt = blockIdx.x;
  if (mt >= g_nmt) return;
  const int e = g_mt_e[mt], row0 = g_mt_r[mt], pend = g_off[e+1];
  const int mrows = g_mt_n[mt];
  const int h0 = blockIdx.y * 128;

  extern __shared__ char smem[];
  const uint32_t sb = smem_u32(smem);
  const int t = threadIdx.x, lane = t & 31, wid = t >> 5;
  const int mw = wid & 3, nw = wid >> 2;       // 4m x 2n warps (32m x 64n each)
  const bool mact = (mw*32 < mrows);

  // ---- producer: 4 threads/row; A 128 rows (2 passes), B 128 rows (2 passes)
  // NOTE: g_act is indexed by grouped row p directly (NO g_perm)
  const int lr = t >> 2, q = t & 3;
  const __half* srcA[2];
  const float*  srcB[2];
  uint32_t sAo[2], sBo[2];
  bool av[2];
  const float* dw_e = DW + (size_t)e*HD*ID;
  #pragma unroll
  for (int j = 0; j < 2; j++){
    int r = lr + j*64;
    av[j] = (r < mrows);
    int p = row0 + r; int pcl = (p < pend) ? p : row0;
    srcA[j] = g_act + (size_t)pcl*ID + q*8;
    srcB[j] = dw_e + (size_t)(h0 + r)*ID + q*8;
    sAo[j] = swz(r) ^ (q << 4);
    sBo[j] = sAo[j] + 8192;
  }

  // ---- consumer fragment offsets ----
  const uint32_t ca = (uint32_t)(lane >> 4) << 4;
  const uint32_t pa0 = swz(mw*32 + (lane & 15)) ^ ca;
  const uint32_t pa1 = swz(mw*32 + 16 + (lane & 15)) ^ ca;
  const int brl = (lane & 7) + (((lane >> 4) & 1) << 3);
  const uint32_t cb = (uint32_t)((lane >> 3) & 1) << 4;
  uint32_t pb[4];
  #pragma unroll
  for (int j = 0; j < 4; j++)
    pb[j] = swz(128 + nw*64 + j*16 + brl) ^ cb;

  float acc[2][8][4] = {};

  // preload
  if (av[0]) sts128(sb + sAo[0], *(const uint4*)srcA[0]);
  if (av[1]) sts128(sb + sAo[1], *(const uint4*)srcA[1]);
  sts128(sb + sBo[0], ld8cvt(srcB[0]));
  sts128(sb + sBo[1], ld8cvt(srcB[1]));
  __syncthreads();

  for (int kt = 0; kt < G2_NKT; kt++){
    const uint32_t sbuf = sb + (uint32_t)(kt & 1)*G2_STAGE;
    uint4 fA0, fA1, fB0, fB1;
    if (kt + 1 < G2_NKT){
      const int ko = (kt + 1)*32;
      if (av[0]) fA0 = *(const uint4*)(srcA[0] + ko);
      if (av[1]) fA1 = *(const uint4*)(srcA[1] + ko);
      fB0 = ld8cvt(srcB[0] + ko);
      fB1 = ld8cvt(srcB[1] + ko);
    }
    if (mact){
      #pragma unroll
      for (int ks = 0; ks < 2; ks++){
        const uint32_t k5 = ((uint32_t)((ks + wid) & 1)) << 5;   // rotated
        uint32_t A0[4], A1[4], B[16];
        ldsm4(A0, sbuf + (pa0 ^ k5));
        ldsm4(A1, sbuf + (pa1 ^ k5));
        #pragma unroll
        for (int j = 0; j < 4; j++) ldsm4(B + j*4, sbuf + (pb[j] ^ k5));
        #pragma unroll
        for (int ni = 0; ni < 8; ni++){
          mma16816(acc[0][ni], A0, B + ni*2);
          mma16816(acc[1][ni], A1, B + ni*2);
        }
      }
    }
    if (kt + 1 < G2_NKT){
      const uint32_t dbuf = sb + (uint32_t)((kt + 1) & 1)*G2_STAGE;
      if (av[0]) sts128(dbuf + sAo[0], fA0);
      if (av[1]) sts128(dbuf + sAo[1], fA1);
      sts128(dbuf + sBo[0], fB0); sts128(dbuf + sBo[1], fB1);
      __syncthreads();
    }
  }

  // ---- epilogue: vector scatter-add into out[token, h] ----
  if (mact){
    const int g = lane >> 2, c = lane & 3;
    #pragma unroll
    for (int mi = 0; mi < 2; mi++){
      #pragma unroll
      for (int h = 0; h < 2; h++){
        int R = mw*32 + mi*16 + g + 8*h;
        int p = row0 + R;
        if (p < pend){
          int tok = g_perm[p];
          float* orow = out + (size_t)tok*HD + h0 + nw*64 + 2*c;
          #pragma unroll
          for (int ni = 0; ni < 8; ni++){
            red2(orow + ni*8, acc[mi][ni][2*h], acc[mi][ni][2*h+1]);
          }
        }
      }
    }
  }
}

// ---------------- launch ----------------
extern "C" void kernel_launch(void* const* d_in, const int* in_sizes, int n_in,
                              void* d_out, int out_size)
{
  const float* X  = (const float*)d_in[0];
  const int*   ix = (const int*)d_in[1];
  const float* tw = (const float*)d_in[2];
  const float* GU = (const float*)d_in[3];
  const float* DW = (const float*)d_in[4];
  float* out = (float*)d_out;
  (void)in_sizes; (void)n_in; (void)out_size;

  cudaFuncSetAttribute(gemm1_kernel, cudaFuncAttributeMaxDynamicSharedMemorySize, G1_SMEM);
  cudaFuncSetAttribute(gemm2_kernel, cudaFuncAttributeMaxDynamicSharedMemorySize, G2_SMEM);

  prep_kernel<<<PREP_NB, 256>>>(X, (float4*)out, ix, tw);
  gemm1_kernel<<<dim3(MAXMT, ID/64),  256, G1_SMEM>>>(GU);
  gemm2_kernel<<<dim3(MAXMT, HD/128), 256, G2_SMEM>>>(DW, out);
}